// round 2
// baseline (speedup 1.0000x reference)
#include <cuda_runtime.h>

// ---------------- model constants ----------------
#define BB      64
#define SS      64
#define DIN     512
#define DATTN   512
#define DMODEL  2048
#define MM      25
#define MP      32       // padded trace depth (1 cache line per (b,d))
#define HEADS   8
#define HD      64
#define NSYNC   512
#define OUT_N   1000
#define TT      50
#define HNLM    32
#define DPRE    2560     // DATTN + DMODEL
#define D2      4096     // 2*DMODEL
#define KS_BIG  8
#define KS_SM   4

#define PRED_SZ   (BB*OUT_N*TT)      // 3,200,000
#define CERT_OFF  (PRED_SZ)
#define SYO_OFF   (PRED_SZ + BB*2*TT)

// ---------------- scratch (device globals; no allocations) ----------------
__device__ float g_kv   [BB*SS*DATTN];
__device__ float g_Kt   [BB*HEADS*HD*SS];   // (b,h,d,s)
__device__ float g_V    [BB*HEADS*SS*HD];   // (b,h,s,d)
__device__ float g_Wqpq [DATTN*DATTN];      // Wqp @ Wq
__device__ float g_bq2  [DATTN];            // bqp@Wq + bq
__device__ float g_Wbig [DPRE*D2];          // rows 0..511 = Wo@Ws1_top ; rows 512.. = Ws1_bot
__device__ float g_bs1c [D2];               // bs1 + bo@Ws1_top
__device__ float g_act  [BB*DMODEL];
__device__ float g_pre  [BB*DPRE];          // [ao | act]
__device__ float g_trace[BB*DMODEL*MP];     // ring buffer
__device__ float g_aA[BB*NSYNC], g_bA[BB*NSYNC];
__device__ float g_aO[BB*NSYNC], g_bO[BB*NSYNC];
__device__ float g_syA[BB*NSYNC], g_syO[BB*NSYNC];
__device__ float g_qpart[KS_SM*BB*DATTN];
__device__ float g_hpart[KS_BIG*BB*D2];
__device__ float g_ppart[KS_SM*BB*OUT_N];

// ---------------- generic fp32 tiled GEMM: C = A(MxK) @ W(KxN) ----------------
// grid.x = ceil(N/64), grid.y = M/64, grid.z = k-split count
// epi: 0 = C[r,c] = acc + bias      (row-major MxN)
//      1 = Kt scatter (b,h,d,s) + bias
//      2 = V  scatter (b,h,s,d) + bias
//      3 = split-K partial: C[(kz*64+r)*N + c] = acc   (requires M=64)
__global__ void gemm_tiled(const float* __restrict__ A, const float* __restrict__ W,
                           float* __restrict__ C, int N, int K,
                           const float* __restrict__ bias, int epi)
{
    __shared__ float As[16][68];
    __shared__ float Ws[16][64];
    const int tid = threadIdx.x;
    const int tx = tid & 15, ty = tid >> 4;
    const int colBase = blockIdx.x * 64;
    const int rowBase = blockIdx.y * 64;
    const int kz = blockIdx.z;
    const int kChunk = K / gridDim.z;
    const int k0 = kz * kChunk;
    const int lr = tid >> 2, lkq = (tid & 3) << 2;   // A tile loader
    const int wk = tid >> 4, wc = (tid & 15) << 2;   // W tile loader

    float acc[4][4];
#pragma unroll
    for (int i = 0; i < 4; i++)
#pragma unroll
        for (int j = 0; j < 4; j++) acc[i][j] = 0.f;

    for (int kk = 0; kk < kChunk; kk += 16) {
        const float4 av = *reinterpret_cast<const float4*>(
            &A[(size_t)(rowBase + lr) * K + (k0 + kk + lkq)]);
        As[lkq+0][lr] = av.x; As[lkq+1][lr] = av.y;
        As[lkq+2][lr] = av.z; As[lkq+3][lr] = av.w;

        const int c4 = colBase + wc;
        const float* wrow = &W[(size_t)(k0 + kk + wk) * N];
        float4 wv;
        if (c4 + 3 < N) {
            wv = *reinterpret_cast<const float4*>(&wrow[c4]);
        } else {
            wv.x = (c4+0 < N) ? wrow[c4+0] : 0.f;
            wv.y = (c4+1 < N) ? wrow[c4+1] : 0.f;
            wv.z = (c4+2 < N) ? wrow[c4+2] : 0.f;
            wv.w = (c4+3 < N) ? wrow[c4+3] : 0.f;
        }
        Ws[wk][wc+0] = wv.x; Ws[wk][wc+1] = wv.y;
        Ws[wk][wc+2] = wv.z; Ws[wk][wc+3] = wv.w;
        __syncthreads();

#pragma unroll
        for (int k = 0; k < 16; k++) {
            const float a0 = As[k][ty*4+0], a1 = As[k][ty*4+1];
            const float a2 = As[k][ty*4+2], a3 = As[k][ty*4+3];
            const float b0 = Ws[k][tx*4+0], b1 = Ws[k][tx*4+1];
            const float b2 = Ws[k][tx*4+2], b3 = Ws[k][tx*4+3];
            acc[0][0] += a0*b0; acc[0][1] += a0*b1; acc[0][2] += a0*b2; acc[0][3] += a0*b3;
            acc[1][0] += a1*b0; acc[1][1] += a1*b1; acc[1][2] += a1*b2; acc[1][3] += a1*b3;
            acc[2][0] += a2*b0; acc[2][1] += a2*b1; acc[2][2] += a2*b2; acc[2][3] += a2*b3;
            acc[3][0] += a3*b0; acc[3][1] += a3*b1; acc[3][2] += a3*b2; acc[3][3] += a3*b3;
        }
        __syncthreads();
    }

#pragma unroll
    for (int i = 0; i < 4; i++) {
        const int r = rowBase + ty*4 + i;
#pragma unroll
        for (int j = 0; j < 4; j++) {
            const int c = colBase + tx*4 + j;
            if (c >= N) continue;
            float v = acc[i][j];
            if (epi == 0) {
                C[(size_t)r * N + c] = v + (bias ? bias[c] : 0.f);
            } else if (epi == 1) {
                const int b = r >> 6, s = r & 63, h = c >> 6, d = c & 63;
                C[((b*HEADS + h)*HD + d)*SS + s] = v + bias[c];
            } else if (epi == 2) {
                const int b = r >> 6, s = r & 63, h = c >> 6, d = c & 63;
                C[((b*HEADS + h)*SS + s)*HD + d] = v + bias[c];
            } else {
                C[((size_t)(kz*64 + r)) * N + c] = v;
            }
        }
    }
}

// ---------------- small helpers ----------------
__global__ void vecmat_kernel(const float* __restrict__ v, const float* __restrict__ W,
                              const float* __restrict__ addin, float* __restrict__ outv,
                              int K, int N)
{
    const int j = blockIdx.x * blockDim.x + threadIdx.x;
    if (j >= N) return;
    float acc = addin ? addin[j] : 0.f;
    for (int i = 0; i < K; i++) acc += v[i] * W[(size_t)i * N + j];
    outv[j] = acc;
}

__global__ void copy_wbig_kernel(const float* __restrict__ Ws1)
{
    const size_t i = (size_t)blockIdx.x * blockDim.x + threadIdx.x;
    const size_t base4 = ((size_t)DATTN * D2) / 4;
    const size_t tot4  = ((size_t)(DPRE - DATTN) * D2) / 4;
    if (i < tot4)
        reinterpret_cast<float4*>(g_Wbig)[base4 + i] =
            reinterpret_cast<const float4*>(Ws1)[base4 + i];
}

__global__ void init_kernel(const float* __restrict__ start_trace,
                            const float* __restrict__ start_state,
                            const int* __restrict__ idx_lo,
                            const int* __restrict__ idx_ro)
{
    const int idx = blockIdx.x * blockDim.x + threadIdx.x;  // over B*DMODEL
    const int b = idx / DMODEL, d = idx - b * DMODEL;
    const float s0 = start_state[d];
    g_act[idx] = s0;
    g_pre[b*DPRE + DATTN + d] = s0;
#pragma unroll
    for (int m = 0; m < MP; m++)
        g_trace[(size_t)idx * MP + m] = (m < MM) ? start_trace[d*MM + m] : 0.f;
    if (d < NSYNC) {
        const int i = d;
        g_aA[b*NSYNC + i] = 0.f;
        g_bA[b*NSYNC + i] = 0.f;
        g_aO[b*NSYNC + i] = start_state[idx_lo[i]] * start_state[idx_ro[i]];
        g_bO[b*NSYNC + i] = 1.f;
    }
}

// mode bit0: sync-A (produces g_syA for next tick); bit1: sync-O (produces g_syO)
__global__ void sync_kernel(const float* __restrict__ decay_a, const float* __restrict__ decay_o,
                            const int* __restrict__ idx_la, const int* __restrict__ idx_ra,
                            const int* __restrict__ idx_lo, const int* __restrict__ idx_ro,
                            int mode)
{
    const int b = blockIdx.x, i = threadIdx.x;
    const float* actb = &g_act[b*DMODEL];
    if (mode & 2) {
        const float pairing = actb[idx_lo[i]] * actb[idx_ro[i]];
        const float r = expf(-fminf(fmaxf(decay_o[i], 0.f), 15.f));
        const float a  = r * g_aO[b*NSYNC + i] + pairing;
        const float bt = r * g_bO[b*NSYNC + i] + 1.f;
        g_aO[b*NSYNC + i] = a;
        g_bO[b*NSYNC + i] = bt;
        g_syO[b*NSYNC + i] = a * rsqrtf(bt);
    }
    if (mode & 1) {
        const float pairing = actb[idx_la[i]] * actb[idx_ra[i]];
        const float r = expf(-fminf(fmaxf(decay_a[i], 0.f), 15.f));
        const float a  = r * g_aA[b*NSYNC + i] + pairing;
        const float bt = r * g_bA[b*NSYNC + i] + 1.f;
        g_aA[b*NSYNC + i] = a;
        g_bA[b*NSYNC + i] = bt;
        g_syA[b*NSYNC + i] = a * rsqrtf(bt);
    }
}

// one block per (h, b); 64 threads
__global__ void attention_kernel(const float* __restrict__ bq2)
{
    const int h = blockIdx.x, b = blockIdx.y;
    const int t = threadIdx.x;
    __shared__ float qs[64];
    __shared__ float ws[64];
    __shared__ float red[4];

    float q = bq2[h*HD + t];
#pragma unroll
    for (int z = 0; z < KS_SM; z++)
        q += g_qpart[(z*BB + b)*DATTN + h*HD + t];
    qs[t] = q;
    __syncthreads();

    const float* ktp = &g_Kt[((b*HEADS + h)*HD) * SS + t];
    float sc = 0.f;
#pragma unroll
    for (int d = 0; d < HD; d++) sc += qs[d] * ktp[d*SS];
    sc *= 0.125f;   // 1/sqrt(64)

    float mx = sc;
#pragma unroll
    for (int off = 16; off; off >>= 1) mx = fmaxf(mx, __shfl_xor_sync(0xffffffffu, mx, off));
    if ((t & 31) == 0) red[t >> 5] = mx;
    __syncthreads();
    mx = fmaxf(red[0], red[1]);

    const float e = expf(sc - mx);
    float sm = e;
#pragma unroll
    for (int off = 16; off; off >>= 1) sm += __shfl_xor_sync(0xffffffffu, sm, off);
    if ((t & 31) == 0) red[2 + (t >> 5)] = sm;
    __syncthreads();
    sm = red[2] + red[3];
    ws[t] = e / sm;
    __syncthreads();

    const float* vp = &g_V[((b*HEADS + h)*SS) * HD + t];
    float ao = 0.f;
#pragma unroll
    for (int s = 0; s < SS; s++) ao += ws[s] * vp[s*HD];
    g_pre[b*DPRE + h*HD + t] = ao;  // ao section of pre
}

// combine split-K partials + bias, GLU, LayerNorm, write into trace ring slot
__global__ void glu_ln_kernel(const float* __restrict__ ln_g, const float* __restrict__ ln_b,
                              int tick)
{
    const int b = blockIdx.x, tid = threadIdx.x;
    __shared__ float gbuf[DMODEL];
    __shared__ float rs[16];
    __shared__ float mu_s, inv_s;

    float s = 0.f, s2 = 0.f;
    for (int j = tid; j < DMODEL; j += 256) {
        float h1 = g_bs1c[j], h2 = g_bs1c[j + DMODEL];
#pragma unroll
        for (int z = 0; z < KS_BIG; z++) {
            const float* hp = &g_hpart[((size_t)(z*BB + b)) * D2];
            h1 += hp[j];
            h2 += hp[j + DMODEL];
        }
        const float g = h1 / (1.f + expf(-h2));  // a1 * sigmoid(a2)
        gbuf[j] = g;
        s += g; s2 += g*g;
    }
#pragma unroll
    for (int off = 16; off; off >>= 1) {
        s  += __shfl_xor_sync(0xffffffffu, s,  off);
        s2 += __shfl_xor_sync(0xffffffffu, s2, off);
    }
    if ((tid & 31) == 0) { rs[tid >> 5] = s; rs[8 + (tid >> 5)] = s2; }
    __syncthreads();
    if (tid == 0) {
        float ts = 0.f, ts2 = 0.f;
        for (int w = 0; w < 8; w++) { ts += rs[w]; ts2 += rs[8 + w]; }
        const float mu = ts / (float)DMODEL;
        const float var = ts2 / (float)DMODEL - mu*mu;
        mu_s = mu;
        inv_s = rsqrtf(var + 1e-5f);
    }
    __syncthreads();
    const int slot = tick % MM;
    for (int j = tid; j < DMODEL; j += 256) {
        const float st = (gbuf[j] - mu_s) * inv_s * ln_g[j] + ln_b[j];
        g_trace[((size_t)(b*DMODEL + j)) * MP + slot] = st;
    }
}

// neuron-level models: one warp per d; lane = hidden unit h (HNLM=32)
__global__ void nlm_kernel(const float* __restrict__ nw1, const float* __restrict__ nb1,
                           const float* __restrict__ nw2, const float* __restrict__ nb2,
                           int tick)
{
    const int lane = threadIdx.x & 31;
    const int wid  = threadIdx.x >> 5;
    const int d = blockIdx.x * 8 + wid;

    float w1[MM];
#pragma unroll
    for (int m = 0; m < MM; m++)
        w1[m] = nw1[((size_t)d*MM + m)*HNLM + lane];
    const float w2 = nw2[d*HNLM + lane];
    const float b1 = nb1[d*HNLM + lane];
    const float b2 = nb2[d];
    const int o = (tick + 1) % MM;   // ring: logical m -> slot (o+m)%MM

    for (int b = 0; b < BB; b++) {
        const float tv = g_trace[((size_t)(b*DMODEL + d)) * MP + lane];
        float acc = b1;
#pragma unroll
        for (int m = 0; m < MM; m++) {
            int sI = o + m; if (sI >= MM) sI -= MM;
            acc += __shfl_sync(0xffffffffu, tv, sI) * w1[m];
        }
        const float x = acc;
        const float th = tanhf(0.7978845608028654f * (x + 0.044715f * x*x*x));
        float val = 0.5f * x * (1.f + th) * w2;
#pragma unroll
        for (int off = 16; off; off >>= 1) val += __shfl_xor_sync(0xffffffffu, val, off);
        if (lane == 0) {
            const float a = val + b2;
            g_act[b*DMODEL + d] = a;
            g_pre[b*DPRE + DATTN + d] = a;
        }
    }
}

// combine pred partials + bias, write predictions, entropy -> certainties
__global__ void entropy_kernel(const float* __restrict__ bout, float* __restrict__ out, int tick)
{
    const int b = blockIdx.x, tid = threadIdx.x;
    __shared__ float pbuf[OUT_N];
    __shared__ float r0[8], r1[8];
    __shared__ float bc;

    float mx = -1e30f;
    for (int o = tid; o < OUT_N; o += 256) {
        float p = bout[o];
#pragma unroll
        for (int z = 0; z < KS_SM; z++) p += g_ppart[(z*BB + b)*OUT_N + o];
        pbuf[o] = p;
        out[((size_t)(b*OUT_N + o)) * TT + tick] = p;
        mx = fmaxf(mx, p);
    }
#pragma unroll
    for (int off = 16; off; off >>= 1) mx = fmaxf(mx, __shfl_xor_sync(0xffffffffu, mx, off));
    if ((tid & 31) == 0) r0[tid >> 5] = mx;
    __syncthreads();
    if (tid == 0) {
        float m = r0[0];
        for (int w = 1; w < 8; w++) m = fmaxf(m, r0[w]);
        bc = m;
    }
    __syncthreads();
    mx = bc;
    __syncthreads();

    float s0 = 0.f, s1 = 0.f;
    for (int o = tid; o < OUT_N; o += 256) {
        const float u = pbuf[o] - mx;
        const float e = expf(u);
        s0 += e;
        s1 += u * e;
    }
#pragma unroll
    for (int off = 16; off; off >>= 1) {
        s0 += __shfl_xor_sync(0xffffffffu, s0, off);
        s1 += __shfl_xor_sync(0xffffffffu, s1, off);
    }
    if ((tid & 31) == 0) { r0[tid >> 5] = s0; r1[tid >> 5] = s1; }
    __syncthreads();
    if (tid == 0) {
        float t0 = 0.f, t1 = 0.f;
        for (int w = 0; w < 8; w++) { t0 += r0[w]; t1 += r1[w]; }
        const float ne = -(t1 / t0 - logf(t0)) / logf((float)OUT_N);
        out[CERT_OFF + (size_t)(b*2 + 0) * TT + tick] = ne;
        out[CERT_OFF + (size_t)(b*2 + 1) * TT + tick] = 1.f - ne;
    }
}

__global__ void final_kernel(float* __restrict__ out)
{
    const int i = blockIdx.x * blockDim.x + threadIdx.x;
    if (i < BB*NSYNC) out[SYO_OFF + i] = g_syO[i];
}

// ---------------- launch ----------------
extern "C" void kernel_launch(void* const* d_in, const int* in_sizes, int n_in,
                              void* d_out, int out_size)
{
    const float* x           = (const float*)d_in[0];
    const float* Wf          = (const float*)d_in[1];
    const float* bf          = (const float*)d_in[2];
    const float* start_trace = (const float*)d_in[3];
    const float* start_state = (const float*)d_in[4];
    const float* decay_a     = (const float*)d_in[5];
    const float* decay_o     = (const float*)d_in[6];
    const float* Wqp         = (const float*)d_in[7];
    const float* bqp         = (const float*)d_in[8];
    const float* Wq          = (const float*)d_in[9];
    const float* bq          = (const float*)d_in[10];
    const float* Wk          = (const float*)d_in[11];
    const float* bk          = (const float*)d_in[12];
    const float* Wv          = (const float*)d_in[13];
    const float* bv          = (const float*)d_in[14];
    const float* Wo          = (const float*)d_in[15];
    const float* bo          = (const float*)d_in[16];
    const float* Ws1         = (const float*)d_in[17];
    const float* bs1         = (const float*)d_in[18];
    const float* ln_g        = (const float*)d_in[19];
    const float* ln_b        = (const float*)d_in[20];
    const float* nw1         = (const float*)d_in[21];
    const float* nb1         = (const float*)d_in[22];
    const float* nw2         = (const float*)d_in[23];
    const float* nb2         = (const float*)d_in[24];
    const float* Wout        = (const float*)d_in[25];
    const float* bout        = (const float*)d_in[26];
    const int*   idx_la      = (const int*)d_in[27];
    const int*   idx_ra      = (const int*)d_in[28];
    const int*   idx_lo      = (const int*)d_in[29];
    const int*   idx_ro      = (const int*)d_in[30];

    float* out = (float*)d_out;

    float* p_kv;    cudaGetSymbolAddress((void**)&p_kv,    g_kv);
    float* p_Kt;    cudaGetSymbolAddress((void**)&p_Kt,    g_Kt);
    float* p_V;     cudaGetSymbolAddress((void**)&p_V,     g_V);
    float* p_Wqpq;  cudaGetSymbolAddress((void**)&p_Wqpq,  g_Wqpq);
    float* p_bq2;   cudaGetSymbolAddress((void**)&p_bq2,   g_bq2);
    float* p_Wbig;  cudaGetSymbolAddress((void**)&p_Wbig,  g_Wbig);
    float* p_bs1c;  cudaGetSymbolAddress((void**)&p_bs1c,  g_bs1c);
    float* p_syA;   cudaGetSymbolAddress((void**)&p_syA,   g_syA);
    float* p_syO;   cudaGetSymbolAddress((void**)&p_syO,   g_syO);
    float* p_pre;   cudaGetSymbolAddress((void**)&p_pre,   g_pre);
    float* p_qpart; cudaGetSymbolAddress((void**)&p_qpart, g_qpart);
    float* p_hpart; cudaGetSymbolAddress((void**)&p_hpart, g_hpart);
    float* p_ppart; cudaGetSymbolAddress((void**)&p_ppart, g_ppart);

    // ---- one-time setup ----
    // kv = x @ Wf + bf
    gemm_tiled<<<dim3(DATTN/64, (BB*SS)/64, 1), 256>>>(x, Wf, p_kv, DATTN, DIN, bf, 0);
    // K (transposed layout), V
    gemm_tiled<<<dim3(DATTN/64, (BB*SS)/64, 1), 256>>>(p_kv, Wk, p_Kt, DATTN, DATTN, bk, 1);
    gemm_tiled<<<dim3(DATTN/64, (BB*SS)/64, 1), 256>>>(p_kv, Wv, p_V,  DATTN, DATTN, bv, 2);
    // fused projection weights
    gemm_tiled<<<dim3(DATTN/64, DATTN/64, 1), 256>>>(Wqp, Wq, p_Wqpq, DATTN, DATTN, (const float*)0, 0);
    gemm_tiled<<<dim3(D2/64, DATTN/64, 1), 256>>>(Wo, Ws1, p_Wbig, D2, DATTN, (const float*)0, 0);
    copy_wbig_kernel<<<2048, 1024>>>(Ws1);
    vecmat_kernel<<<2, 256>>>(bqp, Wq, bq, p_bq2, DATTN, DATTN);
    vecmat_kernel<<<16, 256>>>(bo, Ws1, bs1, p_bs1c, DATTN, D2);
    // recurrent state init
    init_kernel<<<(BB*DMODEL)/256, 256>>>(start_trace, start_state, idx_lo, idx_ro);
    // first A-sync (uses act0)
    sync_kernel<<<BB, NSYNC>>>(decay_a, decay_o, idx_la, idx_ra, idx_lo, idx_ro, 1);

    // ---- 50 recurrent ticks ----
    for (int t = 0; t < TT; t++) {
        // Qh = syA @ (Wqp@Wq)  (split-K partials; bias added in attention)
        gemm_tiled<<<dim3(DATTN/64, 1, KS_SM), 256>>>(p_syA, p_Wqpq, p_qpart,
                                                      DATTN, DATTN, (const float*)0, 3);
        attention_kernel<<<dim3(HEADS, BB), 64>>>(p_bq2);
        // h = pre @ Wbig  (split-K partials)
        gemm_tiled<<<dim3(D2/64, 1, KS_BIG), 256>>>(p_pre, p_Wbig, p_hpart,
                                                    D2, DPRE, (const float*)0, 3);
        glu_ln_kernel<<<BB, 256>>>(ln_g, ln_b, t);
        nlm_kernel<<<DMODEL/8, 256>>>(nw1, nb1, nw2, nb2, t);
        // sync-O for tick t AND sync-A for tick t+1 (both read act_t)
        sync_kernel<<<BB, NSYNC>>>(decay_a, decay_o, idx_la, idx_ra, idx_lo, idx_ro, 3);
        // pred = syO @ Wout (split-K partials; bias in entropy kernel)
        gemm_tiled<<<dim3((OUT_N + 63)/64, 1, KS_SM), 256>>>(p_syO, Wout, p_ppart,
                                                             OUT_N, DATTN, (const float*)0, 3);
        entropy_kernel<<<BB, 256>>>(bout, out, t);
    }

    final_kernel<<<(BB*NSYNC)/256, 256>>>(out);
    (void)in_sizes; (void)n_in; (void)out_size;
}

// round 3
// speedup vs baseline: 1.0054x; 1.0054x over previous
#include <cuda_runtime.h>

// ---------------- model constants ----------------
#define BB      64
#define SS      64
#define DIN     512
#define DATTN   512
#define DMODEL  2048
#define MM      25
#define MP      32       // padded trace depth (1 cache line per (b,d))
#define HEADS   8
#define HD      64
#define NSYNC   512
#define OUT_N   1000
#define TT      50
#define HNLM    32
#define DPRE    2560     // DATTN + DMODEL
#define D2      4096     // 2*DMODEL
#define KS_BIG  8
#define KS_SM   4

#define PRED_SZ   (BB*OUT_N*TT)      // 3,200,000
#define CERT_OFF  (PRED_SZ)
#define SYO_OFF   (PRED_SZ + BB*2*TT)

// ---------------- scratch (device globals; no allocations) ----------------
__device__ float g_kv   [BB*SS*DATTN];
__device__ float g_Kt   [BB*HEADS*HD*SS];   // (b,h,d,s)
__device__ float g_V    [BB*HEADS*SS*HD];   // (b,h,s,d)
__device__ float g_Wqpq [DATTN*DATTN];      // Wqp @ Wq
__device__ float g_bq2  [DATTN];            // bqp@Wq + bq
__device__ float g_Wbig [DPRE*D2];          // rows 0..511 = Wo@Ws1_top ; rows 512.. = Ws1_bot
__device__ float g_bs1c [D2];               // bs1 + bo@Ws1_top
__device__ float g_act  [BB*DMODEL];
__device__ float g_pre  [BB*DPRE];          // [ao | act]
__device__ float g_trace[BB*DMODEL*MP];     // ring buffer
__device__ float g_aA[BB*NSYNC], g_bA[BB*NSYNC];
__device__ float g_aO[BB*NSYNC], g_bO[BB*NSYNC];
__device__ float g_syA[BB*NSYNC], g_syO[BB*NSYNC];
__device__ float g_qpart[KS_SM*BB*DATTN];
__device__ float g_hpart[KS_BIG*BB*D2];
__device__ float g_ppart[KS_SM*BB*OUT_N];

// ---------------- generic fp32 tiled GEMM: C = A(MxK) @ W(KxN) ----------------
// grid.x = ceil(N/64), grid.y = M/64, grid.z = k-split count
// epi: 0 = C[r,c] = acc + bias      (row-major MxN)
//      1 = Kt scatter (b,h,d,s) + bias
//      2 = V  scatter (b,h,s,d) + bias
//      3 = split-K partial: C[(kz*64+r)*N + c] = acc   (requires M=64)
__global__ void gemm_tiled(const float* __restrict__ A, const float* __restrict__ W,
                           float* __restrict__ C, int N, int K,
                           const float* __restrict__ bias, int epi)
{
    __shared__ float As[16][68];
    __shared__ float Ws[16][64];
    const int tid = threadIdx.x;
    const int tx = tid & 15, ty = tid >> 4;
    const int colBase = blockIdx.x * 64;
    const int rowBase = blockIdx.y * 64;
    const int kz = blockIdx.z;
    const int kChunk = K / gridDim.z;
    const int k0 = kz * kChunk;
    const int lr = tid >> 2, lkq = (tid & 3) << 2;   // A tile loader
    const int wk = tid >> 4, wc = (tid & 15) << 2;   // W tile loader

    float acc[4][4];
#pragma unroll
    for (int i = 0; i < 4; i++)
#pragma unroll
        for (int j = 0; j < 4; j++) acc[i][j] = 0.f;

    for (int kk = 0; kk < kChunk; kk += 16) {
        const float4 av = *reinterpret_cast<const float4*>(
            &A[(size_t)(rowBase + lr) * K + (k0 + kk + lkq)]);
        As[lkq+0][lr] = av.x; As[lkq+1][lr] = av.y;
        As[lkq+2][lr] = av.z; As[lkq+3][lr] = av.w;

        const int c4 = colBase + wc;
        const float* wrow = &W[(size_t)(k0 + kk + wk) * N];
        float4 wv;
        if (c4 + 3 < N) {
            wv = *reinterpret_cast<const float4*>(&wrow[c4]);
        } else {
            wv.x = (c4+0 < N) ? wrow[c4+0] : 0.f;
            wv.y = (c4+1 < N) ? wrow[c4+1] : 0.f;
            wv.z = (c4+2 < N) ? wrow[c4+2] : 0.f;
            wv.w = (c4+3 < N) ? wrow[c4+3] : 0.f;
        }
        Ws[wk][wc+0] = wv.x; Ws[wk][wc+1] = wv.y;
        Ws[wk][wc+2] = wv.z; Ws[wk][wc+3] = wv.w;
        __syncthreads();

#pragma unroll
        for (int k = 0; k < 16; k++) {
            const float a0 = As[k][ty*4+0], a1 = As[k][ty*4+1];
            const float a2 = As[k][ty*4+2], a3 = As[k][ty*4+3];
            const float b0 = Ws[k][tx*4+0], b1 = Ws[k][tx*4+1];
            const float b2 = Ws[k][tx*4+2], b3 = Ws[k][tx*4+3];
            acc[0][0] += a0*b0; acc[0][1] += a0*b1; acc[0][2] += a0*b2; acc[0][3] += a0*b3;
            acc[1][0] += a1*b0; acc[1][1] += a1*b1; acc[1][2] += a1*b2; acc[1][3] += a1*b3;
            acc[2][0] += a2*b0; acc[2][1] += a2*b1; acc[2][2] += a2*b2; acc[2][3] += a2*b3;
            acc[3][0] += a3*b0; acc[3][1] += a3*b1; acc[3][2] += a3*b2; acc[3][3] += a3*b3;
        }
        __syncthreads();
    }

#pragma unroll
    for (int i = 0; i < 4; i++) {
        const int r = rowBase + ty*4 + i;
#pragma unroll
        for (int j = 0; j < 4; j++) {
            const int c = colBase + tx*4 + j;
            if (c >= N) continue;
            float v = acc[i][j];
            if (epi == 0) {
                C[(size_t)r * N + c] = v + (bias ? bias[c] : 0.f);
            } else if (epi == 1) {
                const int b = r >> 6, s = r & 63, h = c >> 6, d = c & 63;
                C[((b*HEADS + h)*HD + d)*SS + s] = v + bias[c];
            } else if (epi == 2) {
                const int b = r >> 6, s = r & 63, h = c >> 6, d = c & 63;
                C[((b*HEADS + h)*SS + s)*HD + d] = v + bias[c];
            } else {
                C[((size_t)(kz*64 + r)) * N + c] = v;
            }
        }
    }
}

// ---------------- small helpers ----------------
__global__ void vecmat_kernel(const float* __restrict__ v, const float* __restrict__ W,
                              const float* __restrict__ addin, float* __restrict__ outv,
                              int K, int N)
{
    const int j = blockIdx.x * blockDim.x + threadIdx.x;
    if (j >= N) return;
    float acc = addin ? addin[j] : 0.f;
    for (int i = 0; i < K; i++) acc += v[i] * W[(size_t)i * N + j];
    outv[j] = acc;
}

__global__ void copy_wbig_kernel(const float* __restrict__ Ws1)
{
    const size_t i = (size_t)blockIdx.x * blockDim.x + threadIdx.x;
    const size_t base4 = ((size_t)DATTN * D2) / 4;
    const size_t tot4  = ((size_t)(DPRE - DATTN) * D2) / 4;
    if (i < tot4)
        reinterpret_cast<float4*>(g_Wbig)[base4 + i] =
            reinterpret_cast<const float4*>(Ws1)[base4 + i];
}

__global__ void init_kernel(const float* __restrict__ start_trace,
                            const float* __restrict__ start_state,
                            const int* __restrict__ idx_lo,
                            const int* __restrict__ idx_ro)
{
    const int idx = blockIdx.x * blockDim.x + threadIdx.x;  // over B*DMODEL
    const int b = idx / DMODEL, d = idx - b * DMODEL;
    const float s0 = start_state[d];
    g_act[idx] = s0;
    g_pre[b*DPRE + DATTN + d] = s0;
#pragma unroll
    for (int m = 0; m < MP; m++)
        g_trace[(size_t)idx * MP + m] = (m < MM) ? start_trace[d*MM + m] : 0.f;
    if (d < NSYNC) {
        const int i = d;
        g_aA[b*NSYNC + i] = 0.f;
        g_bA[b*NSYNC + i] = 0.f;
        g_aO[b*NSYNC + i] = start_state[idx_lo[i]] * start_state[idx_ro[i]];
        g_bO[b*NSYNC + i] = 1.f;
    }
}

// mode bit0: sync-A (produces g_syA for next tick); bit1: sync-O (produces g_syO)
__global__ void sync_kernel(const float* __restrict__ decay_a, const float* __restrict__ decay_o,
                            const int* __restrict__ idx_la, const int* __restrict__ idx_ra,
                            const int* __restrict__ idx_lo, const int* __restrict__ idx_ro,
                            int mode)
{
    const int b = blockIdx.x, i = threadIdx.x;
    const float* actb = &g_act[b*DMODEL];
    if (mode & 2) {
        const float pairing = actb[idx_lo[i]] * actb[idx_ro[i]];
        const float r = expf(-fminf(fmaxf(decay_o[i], 0.f), 15.f));
        const float a  = r * g_aO[b*NSYNC + i] + pairing;
        const float bt = r * g_bO[b*NSYNC + i] + 1.f;
        g_aO[b*NSYNC + i] = a;
        g_bO[b*NSYNC + i] = bt;
        g_syO[b*NSYNC + i] = a * rsqrtf(bt);
    }
    if (mode & 1) {
        const float pairing = actb[idx_la[i]] * actb[idx_ra[i]];
        const float r = expf(-fminf(fmaxf(decay_a[i], 0.f), 15.f));
        const float a  = r * g_aA[b*NSYNC + i] + pairing;
        const float bt = r * g_bA[b*NSYNC + i] + 1.f;
        g_aA[b*NSYNC + i] = a;
        g_bA[b*NSYNC + i] = bt;
        g_syA[b*NSYNC + i] = a * rsqrtf(bt);
    }
}

// one block per (h, b); 64 threads
__global__ void attention_kernel(const float* __restrict__ bq2)
{
    const int h = blockIdx.x, b = blockIdx.y;
    const int t = threadIdx.x;
    __shared__ float qs[64];
    __shared__ float ws[64];
    __shared__ float red[4];

    float q = bq2[h*HD + t];
#pragma unroll
    for (int z = 0; z < KS_SM; z++)
        q += g_qpart[(z*BB + b)*DATTN + h*HD + t];
    qs[t] = q;
    __syncthreads();

    const float* ktp = &g_Kt[((b*HEADS + h)*HD) * SS + t];
    float sc = 0.f;
#pragma unroll
    for (int d = 0; d < HD; d++) sc += qs[d] * ktp[d*SS];
    sc *= 0.125f;   // 1/sqrt(64)

    float mx = sc;
#pragma unroll
    for (int off = 16; off; off >>= 1) mx = fmaxf(mx, __shfl_xor_sync(0xffffffffu, mx, off));
    if ((t & 31) == 0) red[t >> 5] = mx;
    __syncthreads();
    mx = fmaxf(red[0], red[1]);

    const float e = expf(sc - mx);
    float sm = e;
#pragma unroll
    for (int off = 16; off; off >>= 1) sm += __shfl_xor_sync(0xffffffffu, sm, off);
    if ((t & 31) == 0) red[2 + (t >> 5)] = sm;
    __syncthreads();
    sm = red[2] + red[3];
    ws[t] = e / sm;
    __syncthreads();

    const float* vp = &g_V[((b*HEADS + h)*SS) * HD + t];
    float ao = 0.f;
#pragma unroll
    for (int s = 0; s < SS; s++) ao += ws[s] * vp[s*HD];
    g_pre[b*DPRE + h*HD + t] = ao;  // ao section of pre
}

// combine split-K partials + bias, GLU, LayerNorm, write into trace ring slot
__global__ void glu_ln_kernel(const float* __restrict__ ln_g, const float* __restrict__ ln_b,
                              int tick)
{
    const int b = blockIdx.x, tid = threadIdx.x;
    __shared__ float gbuf[DMODEL];
    __shared__ float rs[16];
    __shared__ float mu_s, inv_s;

    float s = 0.f, s2 = 0.f;
    for (int j = tid; j < DMODEL; j += 256) {
        float h1 = g_bs1c[j], h2 = g_bs1c[j + DMODEL];
#pragma unroll
        for (int z = 0; z < KS_BIG; z++) {
            const float* hp = &g_hpart[((size_t)(z*BB + b)) * D2];
            h1 += hp[j];
            h2 += hp[j + DMODEL];
        }
        const float g = h1 / (1.f + expf(-h2));  // a1 * sigmoid(a2)
        gbuf[j] = g;
        s += g; s2 += g*g;
    }
#pragma unroll
    for (int off = 16; off; off >>= 1) {
        s  += __shfl_xor_sync(0xffffffffu, s,  off);
        s2 += __shfl_xor_sync(0xffffffffu, s2, off);
    }
    if ((tid & 31) == 0) { rs[tid >> 5] = s; rs[8 + (tid >> 5)] = s2; }
    __syncthreads();
    if (tid == 0) {
        float ts = 0.f, ts2 = 0.f;
        for (int w = 0; w < 8; w++) { ts += rs[w]; ts2 += rs[8 + w]; }
        const float mu = ts / (float)DMODEL;
        const float var = ts2 / (float)DMODEL - mu*mu;
        mu_s = mu;
        inv_s = rsqrtf(var + 1e-5f);
    }
    __syncthreads();
    const int slot = tick % MM;
    for (int j = tid; j < DMODEL; j += 256) {
        const float st = (gbuf[j] - mu_s) * inv_s * ln_g[j] + ln_b[j];
        g_trace[((size_t)(b*DMODEL + j)) * MP + slot] = st;
    }
}

// neuron-level models: one warp per d; lane = hidden unit h (HNLM=32)
__global__ void nlm_kernel(const float* __restrict__ nw1, const float* __restrict__ nb1,
                           const float* __restrict__ nw2, const float* __restrict__ nb2,
                           int tick)
{
    const int lane = threadIdx.x & 31;
    const int wid  = threadIdx.x >> 5;
    const int d = blockIdx.x * 8 + wid;

    float w1[MM];
#pragma unroll
    for (int m = 0; m < MM; m++)
        w1[m] = nw1[((size_t)d*MM + m)*HNLM + lane];
    const float w2 = nw2[d*HNLM + lane];
    const float b1 = nb1[d*HNLM + lane];
    const float b2 = nb2[d];
    const int o = (tick + 1) % MM;   // ring: logical m -> slot (o+m)%MM

    for (int b = 0; b < BB; b++) {
        const float tv = g_trace[((size_t)(b*DMODEL + d)) * MP + lane];
        float acc = b1;
#pragma unroll
        for (int m = 0; m < MM; m++) {
            int sI = o + m; if (sI >= MM) sI -= MM;
            acc += __shfl_sync(0xffffffffu, tv, sI) * w1[m];
        }
        const float x = acc;
        const float th = tanhf(0.7978845608028654f * (x + 0.044715f * x*x*x));
        float val = 0.5f * x * (1.f + th) * w2;
#pragma unroll
        for (int off = 16; off; off >>= 1) val += __shfl_xor_sync(0xffffffffu, val, off);
        if (lane == 0) {
            const float a = val + b2;
            g_act[b*DMODEL + d] = a;
            g_pre[b*DPRE + DATTN + d] = a;
        }
    }
}

// combine pred partials + bias, write predictions, entropy -> certainties
__global__ void entropy_kernel(const float* __restrict__ bout, float* __restrict__ out, int tick)
{
    const int b = blockIdx.x, tid = threadIdx.x;
    __shared__ float pbuf[OUT_N];
    __shared__ float r0[8], r1[8];
    __shared__ float bc;

    float mx = -1e30f;
    for (int o = tid; o < OUT_N; o += 256) {
        float p = bout[o];
#pragma unroll
        for (int z = 0; z < KS_SM; z++) p += g_ppart[(z*BB + b)*OUT_N + o];
        pbuf[o] = p;
        out[((size_t)(b*OUT_N + o)) * TT + tick] = p;
        mx = fmaxf(mx, p);
    }
#pragma unroll
    for (int off = 16; off; off >>= 1) mx = fmaxf(mx, __shfl_xor_sync(0xffffffffu, mx, off));
    if ((tid & 31) == 0) r0[tid >> 5] = mx;
    __syncthreads();
    if (tid == 0) {
        float m = r0[0];
        for (int w = 1; w < 8; w++) m = fmaxf(m, r0[w]);
        bc = m;
    }
    __syncthreads();
    mx = bc;
    __syncthreads();

    float s0 = 0.f, s1 = 0.f;
    for (int o = tid; o < OUT_N; o += 256) {
        const float u = pbuf[o] - mx;
        const float e = expf(u);
        s0 += e;
        s1 += u * e;
    }
#pragma unroll
    for (int off = 16; off; off >>= 1) {
        s0 += __shfl_xor_sync(0xffffffffu, s0, off);
        s1 += __shfl_xor_sync(0xffffffffu, s1, off);
    }
    if ((tid & 31) == 0) { r0[tid >> 5] = s0; r1[tid >> 5] = s1; }
    __syncthreads();
    if (tid == 0) {
        float t0 = 0.f, t1 = 0.f;
        for (int w = 0; w < 8; w++) { t0 += r0[w]; t1 += r1[w]; }
        const float ne = -(t1 / t0 - logf(t0)) / logf((float)OUT_N);
        out[CERT_OFF + (size_t)(b*2 + 0) * TT + tick] = ne;
        out[CERT_OFF + (size_t)(b*2 + 1) * TT + tick] = 1.f - ne;
    }
}

__global__ void final_kernel(float* __restrict__ out)
{
    const int i = blockIdx.x * blockDim.x + threadIdx.x;
    if (i < BB*NSYNC) out[SYO_OFF + i] = g_syO[i];
}

// ---------------- launch ----------------
extern "C" void kernel_launch(void* const* d_in, const int* in_sizes, int n_in,
                              void* d_out, int out_size)
{
    const float* x           = (const float*)d_in[0];
    const float* Wf          = (const float*)d_in[1];
    const float* bf          = (const float*)d_in[2];
    const float* start_trace = (const float*)d_in[3];
    const float* start_state = (const float*)d_in[4];
    const float* decay_a     = (const float*)d_in[5];
    const float* decay_o     = (const float*)d_in[6];
    const float* Wqp         = (const float*)d_in[7];
    const float* bqp         = (const float*)d_in[8];
    const float* Wq          = (const float*)d_in[9];
    const float* bq          = (const float*)d_in[10];
    const float* Wk          = (const float*)d_in[11];
    const float* bk          = (const float*)d_in[12];
    const float* Wv          = (const float*)d_in[13];
    const float* bv          = (const float*)d_in[14];
    const float* Wo          = (const float*)d_in[15];
    const float* bo          = (const float*)d_in[16];
    const float* Ws1         = (const float*)d_in[17];
    const float* bs1         = (const float*)d_in[18];
    const float* ln_g        = (const float*)d_in[19];
    const float* ln_b        = (const float*)d_in[20];
    const float* nw1         = (const float*)d_in[21];
    const float* nb1         = (const float*)d_in[22];
    const float* nw2         = (const float*)d_in[23];
    const float* nb2         = (const float*)d_in[24];
    const float* Wout        = (const float*)d_in[25];
    const float* bout        = (const float*)d_in[26];
    const int*   idx_la      = (const int*)d_in[27];
    const int*   idx_ra      = (const int*)d_in[28];
    const int*   idx_lo      = (const int*)d_in[29];
    const int*   idx_ro      = (const int*)d_in[30];

    float* out = (float*)d_out;

    float* p_kv;    cudaGetSymbolAddress((void**)&p_kv,    g_kv);
    float* p_Kt;    cudaGetSymbolAddress((void**)&p_Kt,    g_Kt);
    float* p_V;     cudaGetSymbolAddress((void**)&p_V,     g_V);
    float* p_Wqpq;  cudaGetSymbolAddress((void**)&p_Wqpq,  g_Wqpq);
    float* p_bq2;   cudaGetSymbolAddress((void**)&p_bq2,   g_bq2);
    float* p_Wbig;  cudaGetSymbolAddress((void**)&p_Wbig,  g_Wbig);
    float* p_bs1c;  cudaGetSymbolAddress((void**)&p_bs1c,  g_bs1c);
    float* p_syA;   cudaGetSymbolAddress((void**)&p_syA,   g_syA);
    float* p_syO;   cudaGetSymbolAddress((void**)&p_syO,   g_syO);
    float* p_pre;   cudaGetSymbolAddress((void**)&p_pre,   g_pre);
    float* p_qpart; cudaGetSymbolAddress((void**)&p_qpart, g_qpart);
    float* p_hpart; cudaGetSymbolAddress((void**)&p_hpart, g_hpart);
    float* p_ppart; cudaGetSymbolAddress((void**)&p_ppart, g_ppart);

    // ---- one-time setup ----
    // kv = x @ Wf + bf
    gemm_tiled<<<dim3(DATTN/64, (BB*SS)/64, 1), 256>>>(x, Wf, p_kv, DATTN, DIN, bf, 0);
    // K (transposed layout), V
    gemm_tiled<<<dim3(DATTN/64, (BB*SS)/64, 1), 256>>>(p_kv, Wk, p_Kt, DATTN, DATTN, bk, 1);
    gemm_tiled<<<dim3(DATTN/64, (BB*SS)/64, 1), 256>>>(p_kv, Wv, p_V,  DATTN, DATTN, bv, 2);
    // fused projection weights
    gemm_tiled<<<dim3(DATTN/64, DATTN/64, 1), 256>>>(Wqp, Wq, p_Wqpq, DATTN, DATTN, (const float*)0, 0);
    gemm_tiled<<<dim3(D2/64, DATTN/64, 1), 256>>>(Wo, Ws1, p_Wbig, D2, DATTN, (const float*)0, 0);
    copy_wbig_kernel<<<2048, 1024>>>(Ws1);
    vecmat_kernel<<<2, 256>>>(bqp, Wq, bq, p_bq2, DATTN, DATTN);
    vecmat_kernel<<<16, 256>>>(bo, Ws1, bs1, p_bs1c, DATTN, D2);
    // recurrent state init
    init_kernel<<<(BB*DMODEL)/256, 256>>>(start_trace, start_state, idx_lo, idx_ro);
    // first A-sync (uses act0)
    sync_kernel<<<BB, NSYNC>>>(decay_a, decay_o, idx_la, idx_ra, idx_lo, idx_ro, 1);

    // ---- 50 recurrent ticks ----
    for (int t = 0; t < TT; t++) {
        // Qh = syA @ (Wqp@Wq)  (split-K partials; bias added in attention)
        gemm_tiled<<<dim3(DATTN/64, 1, KS_SM), 256>>>(p_syA, p_Wqpq, p_qpart,
                                                      DATTN, DATTN, (const float*)0, 3);
        attention_kernel<<<dim3(HEADS, BB), 64>>>(p_bq2);
        // h = pre @ Wbig  (split-K partials)
        gemm_tiled<<<dim3(D2/64, 1, KS_BIG), 256>>>(p_pre, p_Wbig, p_hpart,
                                                    D2, DPRE, (const float*)0, 3);
        glu_ln_kernel<<<BB, 256>>>(ln_g, ln_b, t);
        nlm_kernel<<<DMODEL/8, 256>>>(nw1, nb1, nw2, nb2, t);
        // sync-O for tick t AND sync-A for tick t+1 (both read act_t)
        sync_kernel<<<BB, NSYNC>>>(decay_a, decay_o, idx_la, idx_ra, idx_lo, idx_ro, 3);
        // pred = syO @ Wout (split-K partials; bias in entropy kernel)
        gemm_tiled<<<dim3((OUT_N + 63)/64, 1, KS_SM), 256>>>(p_syO, Wout, p_ppart,
                                                             OUT_N, DATTN, (const float*)0, 3);
        entropy_kernel<<<BB, 256>>>(bout, out, t);
    }

    final_kernel<<<(BB*NSYNC)/256, 256>>>(out);
    (void)in_sizes; (void)n_in; (void)out_size;
}

// round 4
// speedup vs baseline: 1.2292x; 1.2227x over previous
#include <cuda_runtime.h>
#include <cuda_bf16.h>
#include <cstdint>

#define BB 64
#define SS 64
#define DIN 512
#define DATTN 512
#define DMODEL 2048
#define MM 25
#define MP 32
#define HEADS 8
#define HD 64
#define NSYNC 512
#define OUT_N 1000
#define OUT_P 1024
#define TT 50
#define DPRE 2560
#define D2 4096
#define KS 4

#define PRED_SZ (BB*OUT_N*TT)
#define CERT_OFF (PRED_SZ)
#define SYO_OFF (PRED_SZ + BB*2*TT)

// ---------- scratch ----------
__device__ float g_kv[BB*SS*DATTN];
__device__ float g_Kt[BB*HEADS*HD*SS];
__device__ float g_V [BB*HEADS*SS*HD];
__device__ float g_Wqpq[DATTN*DATTN];
__device__ float g_WbigTop[DATTN*D2];
__device__ float g_bq2[DATTN];
__device__ float g_bs1c[D2];
__device__ float g_act[BB*DMODEL];
__device__ float g_trace[BB*DMODEL*MP];
__device__ float g_aA[BB*NSYNC], g_bA[BB*NSYNC];
__device__ float g_aO[BB*NSYNC], g_bO[BB*NSYNC], g_syO[BB*NSYNC];
__device__ float g_qpart[KS*BB*DATTN];
__device__ float g_hpart[KS*BB*D2];
__device__ float g_ppart[KS*BB*OUT_P];
// packed bf16 hi/lo (uint32 = bf162)
__device__ uint32_t g_xp_h[(BB*SS)*(DIN/2)],  g_xp_l[(BB*SS)*(DIN/2)];
__device__ uint32_t g_kvp_h[(BB*SS)*(DATTN/2)], g_kvp_l[(BB*SS)*(DATTN/2)];
__device__ uint32_t g_Wf_h[(DIN/2)*DATTN],  g_Wf_l[(DIN/2)*DATTN];
__device__ uint32_t g_Wk_h[(DATTN/2)*DATTN], g_Wk_l[(DATTN/2)*DATTN];
__device__ uint32_t g_Wv_h[(DATTN/2)*DATTN], g_Wv_l[(DATTN/2)*DATTN];
__device__ uint32_t g_Wq_h[(DATTN/2)*DATTN], g_Wq_l[(DATTN/2)*DATTN];
__device__ uint32_t g_WqpA_h[DATTN*(NSYNC/2)], g_WqpA_l[DATTN*(NSYNC/2)];
__device__ uint32_t g_WoA_h[DATTN*(DATTN/2)], g_WoA_l[DATTN*(DATTN/2)];
__device__ uint32_t g_Ws1t_h[(DATTN/2)*D2], g_Ws1t_l[(DATTN/2)*D2];
__device__ uint32_t g_Wqpq_h[(NSYNC/2)*DATTN], g_Wqpq_l[(NSYNC/2)*DATTN];
__device__ uint32_t g_Wbig_h[(DPRE/2)*D2], g_Wbig_l[(DPRE/2)*D2];
__device__ uint32_t g_Wout_h[(NSYNC/2)*OUT_P], g_Wout_l[(NSYNC/2)*OUT_P];
__device__ uint32_t g_pA_h[BB*(DPRE/2)], g_pA_l[BB*(DPRE/2)];
__device__ uint32_t g_syA_h[BB*(NSYNC/2)], g_syA_l[BB*(NSYNC/2)];
__device__ uint32_t g_syO_h[BB*(NSYNC/2)], g_syO_l[BB*(NSYNC/2)];

// ---------- helpers ----------
__device__ __forceinline__ uint32_t bfpair(float a, float b){
    __nv_bfloat162 t = __floats2bfloat162_rn(a, b);
    return *reinterpret_cast<uint32_t*>(&t);
}
__device__ __forceinline__ void split2(float v0, float v1, uint32_t& hi, uint32_t& lo){
    float h0 = __bfloat162float(__float2bfloat16(v0));
    float h1 = __bfloat162float(__float2bfloat16(v1));
    hi = bfpair(h0, h1);
    lo = bfpair(v0 - h0, v1 - h1);
}
__device__ __forceinline__ void mma16816(float* c, uint32_t a0, uint32_t a1,
                                         uint32_t a2, uint32_t a3, uint32_t b0, uint32_t b1){
    asm volatile("mma.sync.aligned.m16n8k16.row.col.f32.bf16.bf16.f32 "
        "{%0,%1,%2,%3},{%4,%5,%6,%7},{%8,%9},{%0,%1,%2,%3};"
        : "+f"(c[0]), "+f"(c[1]), "+f"(c[2]), "+f"(c[3])
        : "r"(a0), "r"(a1), "r"(a2), "r"(a3), "r"(b0), "r"(b1));
}

// ---------- universal bf16x3 MMA GEMM ----------
// C(MxN) = A(MxK) @ W(KxN). grid=(N/64, M/64, KS). 256 thr.
// epi 0: C=acc+bias  1: Kt scatter  2: V scatter  3: split-K partial (M=64)
__global__ __launch_bounds__(256)
void gemm_mma(const uint32_t* __restrict__ Ah, const uint32_t* __restrict__ Al,
              const uint32_t* __restrict__ Wh, const uint32_t* __restrict__ Wl,
              float* __restrict__ C, const float* __restrict__ bias,
              int N, int K, int epi)
{
    __shared__ uint32_t sAh[64][36], sAl[64][36];
    __shared__ uint32_t sBh[16][72], sBl[16][72];
    const int tid = threadIdx.x;
    const int nBase = blockIdx.x * 64, rowBase = blockIdx.y * 64;
    const int kChunk = K / gridDim.z, k0 = blockIdx.z * kChunk;
    const int Kh = K >> 1;
    const int warp = tid >> 5, lane = tid & 31;
    const int wm = (warp & 3) * 16, wn = (warp >> 2) * 32;
    const int g = lane >> 2, tg = lane & 3;
    float acc[4][4];
#pragma unroll
    for (int t = 0; t < 4; t++){ acc[t][0]=acc[t][1]=acc[t][2]=acc[t][3]=0.f; }

    for (int kk = 0; kk < kChunk; kk += 32){
        const int kpg = (k0 + kk) >> 1;
#pragma unroll
        for (int i = 0; i < 4; i++){
            int idx = tid + i * 256;
            int m = idx >> 4, kp = idx & 15;
            sAh[m][kp] = Ah[(size_t)(rowBase + m) * Kh + kpg + kp];
            sAl[m][kp] = Al[(size_t)(rowBase + m) * Kh + kpg + kp];
            int kb = idx >> 6, n = idx & 63;
            sBh[kb][n] = Wh[(size_t)(kpg + kb) * N + nBase + n];
            sBl[kb][n] = Wl[(size_t)(kpg + kb) * N + nBase + n];
        }
        __syncthreads();
#pragma unroll
        for (int s = 0; s < 2; s++){
            const int kb = s * 8;
            uint32_t ah0 = sAh[wm+g][kb+tg],   ah1 = sAh[wm+8+g][kb+tg];
            uint32_t ah2 = sAh[wm+g][kb+4+tg], ah3 = sAh[wm+8+g][kb+4+tg];
            uint32_t al0 = sAl[wm+g][kb+tg],   al1 = sAl[wm+8+g][kb+tg];
            uint32_t al2 = sAl[wm+g][kb+4+tg], al3 = sAl[wm+8+g][kb+4+tg];
#pragma unroll
            for (int t = 0; t < 4; t++){
                const int n = wn + t * 8 + g;
                uint32_t bh0 = sBh[kb+tg][n], bh1 = sBh[kb+4+tg][n];
                uint32_t bl0 = sBl[kb+tg][n], bl1 = sBl[kb+4+tg][n];
                mma16816(acc[t], ah0, ah1, ah2, ah3, bh0, bh1);
                mma16816(acc[t], ah0, ah1, ah2, ah3, bl0, bl1);
                mma16816(acc[t], al0, al1, al2, al3, bh0, bh1);
            }
        }
        __syncthreads();
    }

    const int r0 = rowBase + wm + g;
#pragma unroll
    for (int t = 0; t < 4; t++){
        const int c = nBase + wn + t * 8 + tg * 2;
#pragma unroll
        for (int hr = 0; hr < 2; hr++){
            const int r = r0 + hr * 8;
            const float v0 = acc[t][hr*2+0], v1 = acc[t][hr*2+1];
            if (epi == 3){
                float* p = &C[((size_t)(blockIdx.z * 64 + (r - rowBase))) * N + c];
                p[0] = v0; p[1] = v1;
            } else if (epi == 0){
                C[(size_t)r*N + c]   = v0 + (bias ? bias[c]   : 0.f);
                C[(size_t)r*N + c+1] = v1 + (bias ? bias[c+1] : 0.f);
            } else if (epi == 1){
                const int b = r >> 6, srow = r & 63, h = c >> 6, d = c & 63;
                C[((b*HEADS+h)*HD + d  )*SS + srow] = v0 + bias[c];
                C[((b*HEADS+h)*HD + d+1)*SS + srow] = v1 + bias[c+1];
            } else {
                const int b = r >> 6, srow = r & 63, h = c >> 6, d = c & 63;
                C[((b*HEADS+h)*SS + srow)*HD + d  ] = v0 + bias[c];
                C[((b*HEADS+h)*SS + srow)*HD + d+1] = v1 + bias[c+1];
            }
        }
    }
}

// ---------- packing ----------
__global__ void packA_kernel(const float* __restrict__ src, uint32_t* __restrict__ h,
                             uint32_t* __restrict__ l, int M, int K)
{
    int idx = blockIdx.x * 256 + threadIdx.x;
    int Kh = K >> 1;
    if (idx >= M * Kh) return;
    int m = idx / Kh, kp = idx - m * Kh;
    split2(src[(size_t)m*K + 2*kp], src[(size_t)m*K + 2*kp + 1], h[idx], l[idx]);
}
__global__ void packW_kernel(const float* __restrict__ src, uint32_t* __restrict__ h,
                             uint32_t* __restrict__ l, int Ns, int Nd, int Kd)
{
    int idx = blockIdx.x * 256 + threadIdx.x;
    if (idx >= (Kd/2) * Nd) return;
    int kp = idx / Nd, n = idx - kp * Nd;
    float v0 = (n < Ns) ? src[(size_t)(2*kp)*Ns + n] : 0.f;
    float v1 = (n < Ns) ? src[(size_t)(2*kp+1)*Ns + n] : 0.f;
    split2(v0, v1, h[idx], l[idx]);
}
__global__ void packWbig_kernel(const float* __restrict__ Ws1)
{
    int idx = blockIdx.x * 256 + threadIdx.x;  // (DPRE/2)*D2 grid covers exactly
    int kp = idx / D2, n = idx - kp * D2;
    float v0, v1;
    if (kp < DATTN/2){ v0 = g_WbigTop[(size_t)(2*kp)*D2 + n]; v1 = g_WbigTop[(size_t)(2*kp+1)*D2 + n]; }
    else             { v0 = Ws1[(size_t)(2*kp)*D2 + n];       v1 = Ws1[(size_t)(2*kp+1)*D2 + n]; }
    split2(v0, v1, g_Wbig_h[idx], g_Wbig_l[idx]);
}

// ---------- small kernels ----------
__global__ void vecmat_kernel(const float* __restrict__ v, const float* __restrict__ W,
                              const float* __restrict__ addin, float* __restrict__ outv,
                              int K, int N)
{
    const int j = blockIdx.x * blockDim.x + threadIdx.x;
    if (j >= N) return;
    float acc = addin ? addin[j] : 0.f;
    for (int i = 0; i < K; i++) acc += v[i] * W[(size_t)i * N + j];
    outv[j] = acc;
}

__global__ void init_kernel(const float* __restrict__ start_trace,
                            const float* __restrict__ start_state,
                            const int* __restrict__ idx_lo, const int* __restrict__ idx_ro)
{
    const int idx = blockIdx.x * blockDim.x + threadIdx.x;  // B*DMODEL
    const int b = idx / DMODEL, d = idx - b * DMODEL;
    const float s0 = start_state[d];
    g_act[idx] = s0;
    if (!(d & 1)){
        uint32_t h, l; split2(s0, start_state[d+1], h, l);
        const int kp = (DATTN + d) >> 1;
        g_pA_h[b*(DPRE/2) + kp] = h; g_pA_l[b*(DPRE/2) + kp] = l;
    }
#pragma unroll
    for (int m = 0; m < MP; m++)
        g_trace[(size_t)idx * MP + m] = (m < MM) ? start_trace[d*MM + m] : 0.f;
    if (d < NSYNC){
        g_aA[b*NSYNC + d] = 0.f; g_bA[b*NSYNC + d] = 0.f;
        g_aO[b*NSYNC + d] = start_state[idx_lo[d]] * start_state[idx_ro[d]];
        g_bO[b*NSYNC + d] = 1.f;
    }
}

__global__ void sync_kernel(const float* __restrict__ decay_a, const float* __restrict__ decay_o,
                            const int* __restrict__ idx_la, const int* __restrict__ idx_ra,
                            const int* __restrict__ idx_lo, const int* __restrict__ idx_ro,
                            int mode)
{
    const int b = blockIdx.x, i = threadIdx.x;
    const float* actb = &g_act[b*DMODEL];
    if (mode & 2){
        const float pairing = actb[idx_lo[i]] * actb[idx_ro[i]];
        const float r = __expf(-fminf(fmaxf(decay_o[i], 0.f), 15.f));
        const float a = r * g_aO[b*NSYNC+i] + pairing;
        const float bt = r * g_bO[b*NSYNC+i] + 1.f;
        g_aO[b*NSYNC+i] = a; g_bO[b*NSYNC+i] = bt;
        const float v = a * rsqrtf(bt);
        g_syO[b*NSYNC+i] = v;
        const float vn = __shfl_down_sync(0xffffffffu, v, 1);
        if (!(i & 1)){
            uint32_t h, l; split2(v, vn, h, l);
            g_syO_h[b*(NSYNC/2) + (i>>1)] = h; g_syO_l[b*(NSYNC/2) + (i>>1)] = l;
        }
    }
    if (mode & 1){
        const float pairing = actb[idx_la[i]] * actb[idx_ra[i]];
        const float r = __expf(-fminf(fmaxf(decay_a[i], 0.f), 15.f));
        const float a = r * g_aA[b*NSYNC+i] + pairing;
        const float bt = r * g_bA[b*NSYNC+i] + 1.f;
        g_aA[b*NSYNC+i] = a; g_bA[b*NSYNC+i] = bt;
        const float v = a * rsqrtf(bt);
        const float vn = __shfl_down_sync(0xffffffffu, v, 1);
        if (!(i & 1)){
            uint32_t h, l; split2(v, vn, h, l);
            g_syA_h[b*(NSYNC/2) + (i>>1)] = h; g_syA_l[b*(NSYNC/2) + (i>>1)] = l;
        }
    }
}

__global__ void attention_kernel(const float* __restrict__ bq2)
{
    const int h = blockIdx.x, b = blockIdx.y, t = threadIdx.x;
    __shared__ float qs[64], ws[64], red[4];

    float q = bq2[h*HD + t];
#pragma unroll
    for (int z = 0; z < KS; z++) q += g_qpart[(z*BB + b)*DATTN + h*HD + t];
    qs[t] = q;
    __syncthreads();

    const float* ktp = &g_Kt[((b*HEADS + h)*HD) * SS + t];
    float sc = 0.f;
#pragma unroll
    for (int d = 0; d < HD; d++) sc += qs[d] * ktp[d*SS];
    sc *= 0.125f;

    float mx = sc;
#pragma unroll
    for (int off = 16; off; off >>= 1) mx = fmaxf(mx, __shfl_xor_sync(0xffffffffu, mx, off));
    if ((t & 31) == 0) red[t >> 5] = mx;
    __syncthreads();
    mx = fmaxf(red[0], red[1]);
    const float e = __expf(sc - mx);
    float sm = e;
#pragma unroll
    for (int off = 16; off; off >>= 1) sm += __shfl_xor_sync(0xffffffffu, sm, off);
    if ((t & 31) == 0) red[2 + (t >> 5)] = sm;
    __syncthreads();
    sm = red[2] + red[3];
    ws[t] = e / sm;
    __syncthreads();

    const float* vp = &g_V[((b*HEADS + h)*SS) * HD + t];
    float ao = 0.f;
#pragma unroll
    for (int s = 0; s < SS; s++) ao += ws[s] * vp[s*HD];

    const float an = __shfl_down_sync(0xffffffffu, ao, 1);
    if (!(t & 1)){
        uint32_t hi, lo; split2(ao, an, hi, lo);
        const int kp = (h*HD + t) >> 1;
        g_pA_h[b*(DPRE/2) + kp] = hi; g_pA_l[b*(DPRE/2) + kp] = lo;
    }
}

__global__ void glu_ln_kernel(const float* __restrict__ ln_g, const float* __restrict__ ln_b, int tick)
{
    const int b = blockIdx.x, tid = threadIdx.x;
    __shared__ float gbuf[DMODEL];
    __shared__ float rs[16];
    __shared__ float mu_s, inv_s;

    float s = 0.f, s2 = 0.f;
    for (int j = tid; j < DMODEL; j += 256){
        float h1 = g_bs1c[j], h2 = g_bs1c[j + DMODEL];
#pragma unroll
        for (int z = 0; z < KS; z++){
            const float* hp = &g_hpart[((size_t)(z*BB + b)) * D2];
            h1 += hp[j]; h2 += hp[j + DMODEL];
        }
        const float gv = h1 / (1.f + __expf(-h2));
        gbuf[j] = gv; s += gv; s2 += gv*gv;
    }
#pragma unroll
    for (int off = 16; off; off >>= 1){
        s  += __shfl_xor_sync(0xffffffffu, s,  off);
        s2 += __shfl_xor_sync(0xffffffffu, s2, off);
    }
    if ((tid & 31) == 0){ rs[tid>>5] = s; rs[8 + (tid>>5)] = s2; }
    __syncthreads();
    if (tid == 0){
        float ts = 0.f, ts2 = 0.f;
        for (int w = 0; w < 8; w++){ ts += rs[w]; ts2 += rs[8+w]; }
        const float mu = ts / (float)DMODEL;
        mu_s = mu; inv_s = rsqrtf(ts2 / (float)DMODEL - mu*mu + 1e-5f);
    }
    __syncthreads();
    const int slot = tick % MM;
    for (int j = tid; j < DMODEL; j += 256)
        g_trace[((size_t)(b*DMODEL + j)) * MP + slot] = (gbuf[j] - mu_s) * inv_s * ln_g[j] + ln_b[j];
}

__global__ void nlm_kernel(const float* __restrict__ nw1, const float* __restrict__ nb1,
                           const float* __restrict__ nw2, const float* __restrict__ nb2, int tick)
{
    const int lane = threadIdx.x & 31, wid = threadIdx.x >> 5;
    const int d = blockIdx.x * 8 + wid;
    __shared__ float sAct[8][64];

    float w1[MM];
#pragma unroll
    for (int m = 0; m < MM; m++) w1[m] = nw1[((size_t)d*MM + m)*32 + lane];
    const float w2 = nw2[d*32 + lane];
    const float b1 = nb1[d*32 + lane];
    const float b2 = nb2[d];
    const int o = (tick + 1) % MM;

    for (int b = 0; b < BB; b++){
        const float tv = g_trace[((size_t)(b*DMODEL + d)) * MP + lane];
        float acc = b1;
#pragma unroll
        for (int m = 0; m < MM; m++){
            int sI = o + m; if (sI >= MM) sI -= MM;
            acc += __shfl_sync(0xffffffffu, tv, sI) * w1[m];
        }
        const float x = acc;
        const float z = 0.7978845608028654f * (x + 0.044715f * x*x*x);
        const float ee = __expf(-2.f * fabsf(z));
        const float th = copysignf((1.f - ee) / (1.f + ee), z);
        float val = 0.5f * x * (1.f + th) * w2;
#pragma unroll
        for (int off = 16; off; off >>= 1) val += __shfl_xor_sync(0xffffffffu, val, off);
        if (lane == 0){
            const float a = val + b2;
            g_act[b*DMODEL + d] = a;
            sAct[wid][b] = a;
        }
    }
    __syncthreads();
    {
        const int p = threadIdx.x & 3, b = threadIdx.x >> 2;
        const float v0 = sAct[2*p][b], v1 = sAct[2*p+1][b];
        uint32_t hi, lo; split2(v0, v1, hi, lo);
        const int kp = (DATTN >> 1) + blockIdx.x * 4 + p;
        g_pA_h[b*(DPRE/2) + kp] = hi; g_pA_l[b*(DPRE/2) + kp] = lo;
    }
}

__global__ void entropy_kernel(const float* __restrict__ bout, float* __restrict__ out, int tick)
{
    const int b = blockIdx.x, tid = threadIdx.x;
    __shared__ float pbuf[OUT_N];
    __shared__ float r0[8], r1[8];
    __shared__ float bc;

    float mx = -1e30f;
    for (int o = tid; o < OUT_N; o += 256){
        float p = bout[o];
#pragma unroll
        for (int z = 0; z < KS; z++) p += g_ppart[(z*BB + b)*OUT_P + o];
        pbuf[o] = p;
        out[((size_t)(b*OUT_N + o)) * TT + tick] = p;
        mx = fmaxf(mx, p);
    }
#pragma unroll
    for (int off = 16; off; off >>= 1) mx = fmaxf(mx, __shfl_xor_sync(0xffffffffu, mx, off));
    if ((tid & 31) == 0) r0[tid >> 5] = mx;
    __syncthreads();
    if (tid == 0){
        float m = r0[0];
        for (int w = 1; w < 8; w++) m = fmaxf(m, r0[w]);
        bc = m;
    }
    __syncthreads();
    mx = bc;

    float s0 = 0.f, s1 = 0.f;
    for (int o = tid; o < OUT_N; o += 256){
        const float u = pbuf[o] - mx;
        const float e = __expf(u);
        s0 += e; s1 += u * e;
    }
#pragma unroll
    for (int off = 16; off; off >>= 1){
        s0 += __shfl_xor_sync(0xffffffffu, s0, off);
        s1 += __shfl_xor_sync(0xffffffffu, s1, off);
    }
    if ((tid & 31) == 0){ r0[tid>>5] = s0; r1[tid>>5] = s1; }
    __syncthreads();
    if (tid == 0){
        float t0 = 0.f, t1 = 0.f;
        for (int w = 0; w < 8; w++){ t0 += r0[w]; t1 += r1[w]; }
        const float ne = -(t1 / t0 - logf(t0)) / logf((float)OUT_N);
        out[CERT_OFF + (size_t)(b*2 + 0) * TT + tick] = ne;
        out[CERT_OFF + (size_t)(b*2 + 1) * TT + tick] = 1.f - ne;
    }
}

__global__ void final_kernel(float* __restrict__ out)
{
    const int i = blockIdx.x * blockDim.x + threadIdx.x;
    if (i < BB*NSYNC) out[SYO_OFF + i] = g_syO[i];
}

// ---------- launch ----------
extern "C" void kernel_launch(void* const* d_in, const int* in_sizes, int n_in,
                              void* d_out, int out_size)
{
    const float* x   = (const float*)d_in[0];
    const float* Wf  = (const float*)d_in[1];
    const float* bf  = (const float*)d_in[2];
    const float* start_trace = (const float*)d_in[3];
    const float* start_state = (const float*)d_in[4];
    const float* decay_a = (const float*)d_in[5];
    const float* decay_o = (const float*)d_in[6];
    const float* Wqp = (const float*)d_in[7];
    const float* bqp = (const float*)d_in[8];
    const float* Wq  = (const float*)d_in[9];
    const float* bq  = (const float*)d_in[10];
    const float* Wk  = (const float*)d_in[11];
    const float* bk  = (const float*)d_in[12];
    const float* Wv  = (const float*)d_in[13];
    const float* bv  = (const float*)d_in[14];
    const float* Wo  = (const float*)d_in[15];
    const float* bo  = (const float*)d_in[16];
    const float* Ws1 = (const float*)d_in[17];
    const float* bs1 = (const float*)d_in[18];
    const float* ln_g = (const float*)d_in[19];
    const float* ln_b = (const float*)d_in[20];
    const float* nw1 = (const float*)d_in[21];
    const float* nb1 = (const float*)d_in[22];
    const float* nw2 = (const float*)d_in[23];
    const float* nb2 = (const float*)d_in[24];
    const float* Wout = (const float*)d_in[25];
    const float* bout = (const float*)d_in[26];
    const int* idx_la = (const int*)d_in[27];
    const int* idx_ra = (const int*)d_in[28];
    const int* idx_lo = (const int*)d_in[29];
    const int* idx_ro = (const int*)d_in[30];
    float* out = (float*)d_out;

#define SYM(p, s) float* p; cudaGetSymbolAddress((void**)&p, s)
#define SYMU(p, s) uint32_t* p; cudaGetSymbolAddress((void**)&p, s)
    SYM(p_kv, g_kv); SYM(p_Kt, g_Kt); SYM(p_V, g_V);
    SYM(p_Wqpq, g_Wqpq); SYM(p_WbigTop, g_WbigTop);
    SYM(p_bq2, g_bq2); SYM(p_bs1c, g_bs1c);
    SYM(p_qpart, g_qpart); SYM(p_hpart, g_hpart); SYM(p_ppart, g_ppart);
    SYMU(p_xph, g_xp_h); SYMU(p_xpl, g_xp_l);
    SYMU(p_kvh, g_kvp_h); SYMU(p_kvl, g_kvp_l);
    SYMU(p_Wfh, g_Wf_h); SYMU(p_Wfl, g_Wf_l);
    SYMU(p_Wkh, g_Wk_h); SYMU(p_Wkl, g_Wk_l);
    SYMU(p_Wvh, g_Wv_h); SYMU(p_Wvl, g_Wv_l);
    SYMU(p_Wqh, g_Wq_h); SYMU(p_Wql, g_Wq_l);
    SYMU(p_WqpAh, g_WqpA_h); SYMU(p_WqpAl, g_WqpA_l);
    SYMU(p_WoAh, g_WoA_h); SYMU(p_WoAl, g_WoA_l);
    SYMU(p_Ws1th, g_Ws1t_h); SYMU(p_Ws1tl, g_Ws1t_l);
    SYMU(p_Wqpqh, g_Wqpq_h); SYMU(p_Wqpql, g_Wqpq_l);
    SYMU(p_Wbigh, g_Wbig_h); SYMU(p_Wbigl, g_Wbig_l);
    SYMU(p_Wouth, g_Wout_h); SYMU(p_Woutl, g_Wout_l);
    SYMU(p_pAh, g_pA_h); SYMU(p_pAl, g_pA_l);
    SYMU(p_syAh, g_syA_h); SYMU(p_syAl, g_syA_l);
    SYMU(p_syOh, g_syO_h); SYMU(p_syOl, g_syO_l);
#undef SYM
#undef SYMU

    // ---- setup: pack inputs ----
    packA_kernel<<<(BB*SS*(DIN/2))/256, 256>>>(x, p_xph, p_xpl, BB*SS, DIN);
    packW_kernel<<<((DIN/2)*DATTN)/256, 256>>>(Wf, p_Wfh, p_Wfl, DATTN, DATTN, DIN);
    packW_kernel<<<((DATTN/2)*DATTN)/256, 256>>>(Wk, p_Wkh, p_Wkl, DATTN, DATTN, DATTN);
    packW_kernel<<<((DATTN/2)*DATTN)/256, 256>>>(Wv, p_Wvh, p_Wvl, DATTN, DATTN, DATTN);
    packW_kernel<<<((DATTN/2)*DATTN)/256, 256>>>(Wq, p_Wqh, p_Wql, DATTN, DATTN, DATTN);
    packA_kernel<<<(DATTN*(NSYNC/2))/256, 256>>>(Wqp, p_WqpAh, p_WqpAl, NSYNC, DATTN);
    packA_kernel<<<(DATTN*(DATTN/2))/256, 256>>>(Wo, p_WoAh, p_WoAl, DATTN, DATTN);
    packW_kernel<<<((DATTN/2)*D2)/256, 256>>>(Ws1, p_Ws1th, p_Ws1tl, D2, D2, DATTN);
    packW_kernel<<<((NSYNC/2)*OUT_P)/256, 256>>>(Wout, p_Wouth, p_Woutl, OUT_N, OUT_P, NSYNC);

    // ---- setup: GEMMs ----
    gemm_mma<<<dim3(DATTN/64, (BB*SS)/64, 1), 256>>>(p_xph, p_xpl, p_Wfh, p_Wfl, p_kv, bf, DATTN, DIN, 0);
    packA_kernel<<<(BB*SS*(DATTN/2))/256, 256>>>(p_kv, p_kvh, p_kvl, BB*SS, DATTN);
    gemm_mma<<<dim3(DATTN/64, (BB*SS)/64, 1), 256>>>(p_kvh, p_kvl, p_Wkh, p_Wkl, p_Kt, bk, DATTN, DATTN, 1);
    gemm_mma<<<dim3(DATTN/64, (BB*SS)/64, 1), 256>>>(p_kvh, p_kvl, p_Wvh, p_Wvl, p_V,  bv, DATTN, DATTN, 2);
    gemm_mma<<<dim3(DATTN/64, NSYNC/64, 1), 256>>>(p_WqpAh, p_WqpAl, p_Wqh, p_Wql, p_Wqpq, (const float*)0, DATTN, DATTN, 0);
    packW_kernel<<<((NSYNC/2)*DATTN)/256, 256>>>(p_Wqpq, p_Wqpqh, p_Wqpql, DATTN, DATTN, NSYNC);
    gemm_mma<<<dim3(D2/64, DATTN/64, 1), 256>>>(p_WoAh, p_WoAl, p_Ws1th, p_Ws1tl, p_WbigTop, (const float*)0, D2, DATTN, 0);
    packWbig_kernel<<<((DPRE/2)*D2)/256, 256>>>(Ws1);
    vecmat_kernel<<<2, 256>>>(bqp, Wq, bq, p_bq2, DATTN, DATTN);
    vecmat_kernel<<<16, 256>>>(bo, Ws1, bs1, p_bs1c, DATTN, D2);
    init_kernel<<<(BB*DMODEL)/256, 256>>>(start_trace, start_state, idx_lo, idx_ro);
    sync_kernel<<<BB, NSYNC>>>(decay_a, decay_o, idx_la, idx_ra, idx_lo, idx_ro, 1);

    // ---- 50 ticks ----
    for (int t = 0; t < TT; t++){
        gemm_mma<<<dim3(DATTN/64, 1, KS), 256>>>(p_syAh, p_syAl, p_Wqpqh, p_Wqpql,
                                                 p_qpart, (const float*)0, DATTN, NSYNC, 3);
        attention_kernel<<<dim3(HEADS, BB), 64>>>(p_bq2);
        gemm_mma<<<dim3(D2/64, 1, KS), 256>>>(p_pAh, p_pAl, p_Wbigh, p_Wbigl,
                                              p_hpart, (const float*)0, D2, DPRE, 3);
        glu_ln_kernel<<<BB, 256>>>(ln_g, ln_b, t);
        nlm_kernel<<<DMODEL/8, 256>>>(nw1, nb1, nw2, nb2, t);
        sync_kernel<<<BB, NSYNC>>>(decay_a, decay_o, idx_la, idx_ra, idx_lo, idx_ro, 3);
        gemm_mma<<<dim3(OUT_P/64, 1, KS), 256>>>(p_syOh, p_syOl, p_Wouth, p_Woutl,
                                                 p_ppart, (const float*)0, OUT_P, NSYNC, 3);
        entropy_kernel<<<BB, 256>>>(bout, out, t);
    }
    final_kernel<<<(BB*NSYNC)/256, 256>>>(out);
    (void)in_sizes; (void)n_in; (void)out_size;
}